// round 6
// baseline (speedup 1.0000x reference)
#include <cuda_runtime.h>

#define NN 50000
#define EE 800000
#define DD 96
#define NV4 (NN * DD / 4)

// ---------------- scratch (device globals; no allocation allowed) ----------
__device__ __align__(256) float g_deg[NN];
__device__ __align__(256) float g_dis[NN];
__device__ __align__(256) uint2 g_edge[EE];      // {(r<<16)|c, norm bits}
__device__ __align__(256) float g_T1[NN * DD];
__device__ __align__(256) float g_P[NN * DD];
__device__ __align__(256) float g_acc[NN * DD];  // running pre-BN output
__device__ __align__(256) float g_colsum[DD];
__device__ __align__(256) float g_colsumsq[DD];
__device__ __align__(256) float g_scale[DD];
__device__ __align__(256) float g_shift[DD];

// ---------------- packed f32x2 FMA (SASS FFMA2) -----------------------------
__device__ __forceinline__ void ffma2(unsigned long long& d,
                                      unsigned long long a,
                                      unsigned long long b) {
    asm("fma.rn.f32x2 %0, %1, %2, %0;" : "+l"(d) : "l"(a), "l"(b));
}

// ---------------- zero scratch ---------------------------------------------
__global__ void zero_kernel() {
    int tid = blockIdx.x * blockDim.x + threadIdx.x;
    int stride = gridDim.x * blockDim.x;
    float4* t1 = reinterpret_cast<float4*>(g_T1);
    float4* p  = reinterpret_cast<float4*>(g_P);
    float4 z = make_float4(0.f, 0.f, 0.f, 0.f);
    for (int i = tid; i < NV4; i += stride) { t1[i] = z; p[i] = z; }
    for (int i = tid; i < NN; i += stride) g_deg[i] = 0.f;
    if (tid < DD) { g_colsum[tid] = 0.f; g_colsumsq[tid] = 0.f; }
}

// ---------------- degree / normalization -----------------------------------
__global__ void deg_kernel(const int* __restrict__ ei) {
    int e = blockIdx.x * blockDim.x + threadIdx.x;
    if (e >= EE) return;
    int r = ei[e], c = ei[EE + e];
    if (r != c) atomicAdd(&g_deg[r], 1.0f);
}

__global__ void dis_kernel() {
    int i = blockIdx.x * blockDim.x + threadIdx.x;
    if (i >= NN) return;
    float d = g_deg[i];
    g_dis[i] = (d > 0.f) ? rsqrtf(fmaxf(d, 1e-12f)) : 0.f;
}

__global__ void edge_build_kernel(const int* __restrict__ ei) {
    int e = blockIdx.x * blockDim.x + threadIdx.x;
    if (e >= EE) return;
    int r = ei[e], c = ei[EE + e];
    float nrm = (r != c) ? (-g_dis[r] * g_dis[c]) : 0.f;
    g_edge[e] = make_uint2(((unsigned)r << 16) | (unsigned)c,
                           (unsigned)__float_as_int(nrm));
}

// ---------------- GEMM tile config -----------------------------------------
#define GT 192              // threads per block
#define RPB 64              // rows per tile
#define WS_STRIDE 100
#define GBLK ((NN + RPB - 1) / RPB)              // 782 tiles
#define SMEM_FLOATS (DD * WS_STRIDE + DD + RPB * DD)   // 9600 + 96 + 6144
#define SMEM_BYTES (SMEM_FLOATS * 4)             // 63360 B -> 3 CTAs/SM

// One accumulation pass: g_acc (+)= src @ Wm [+ bias].
// mode 0: src=x, init=bias, write acc
// mode 1: src=T1, acc += , write acc
// mode 2: src=2P-x (staged), acc += , write acc + BN stats
__device__ __forceinline__ void gemm_tile(float* smem, int tile, int mode,
                                          const float* __restrict__ x,
                                          const float* __restrict__ Wm,
                                          const float* __restrict__ bias) {
    float* Ws = smem;                    // [96*100] transposed
    float* bs = Ws + DD * WS_STRIDE;     // [96]
    float* xs = bs + DD;                 // [64*96]

    int tid = threadIdx.x;

    // stage Wm transposed: Ws[j*100 + k] = Wm[k*96 + j]
    for (int i = tid; i < DD * DD; i += GT) {
        int k = i / DD, j = i - k * DD;
        Ws[j * WS_STRIDE + k] = Wm[i];
    }
    if (mode == 0 && tid < DD) bs[tid] = bias[tid];

    int base = tile * RPB;

    // stage 64 rows of src
    {
        float4* xs4 = reinterpret_cast<float4*>(xs);
        const float4* x4 = reinterpret_cast<const float4*>(x);
        const float4* t14 = reinterpret_cast<const float4*>(g_T1);
        const float4* p4 = reinterpret_cast<const float4*>(g_P);
        for (int i = tid; i < RPB * (DD / 4); i += GT) {
            int r = i / (DD / 4);
            int row = base + r;
            float4 v = make_float4(0.f, 0.f, 0.f, 0.f);
            if (row < NN) {
                int gi = row * (DD / 4) + (i - r * (DD / 4));
                if (mode == 0) v = __ldg(x4 + gi);
                else if (mode == 1) v = t14[gi];
                else {
                    float4 pv = p4[gi];
                    float4 xv = __ldg(x4 + gi);
                    v = make_float4(2.f * pv.x - xv.x, 2.f * pv.y - xv.y,
                                    2.f * pv.z - xv.z, 2.f * pv.w - xv.w);
                }
            }
            xs4[i] = v;
        }
    }
    __syncthreads();

    int tx = tid % 24;          // j in {tx, tx+24, tx+48, tx+72}
    int ty = tid / 24;          // rows base + ty*8 .. +8

    unsigned long long acc[8][4];
#pragma unroll
    for (int r = 0; r < 8; r++)
#pragma unroll
        for (int jj = 0; jj < 4; jj++) acc[r][jj] = 0ULL;

    const float* xrow = xs + ty * 8 * DD;

    for (int k = 0; k < DD; k += 4) {
        ulonglong2 w[4];
#pragma unroll
        for (int jj = 0; jj < 4; jj++)
            w[jj] = *reinterpret_cast<const ulonglong2*>(
                        &Ws[(tx + jj * 24) * WS_STRIDE + k]);
#pragma unroll
        for (int r = 0; r < 8; r++) {
            ulonglong2 xv = *reinterpret_cast<const ulonglong2*>(&xrow[r * DD + k]);
#pragma unroll
            for (int jj = 0; jj < 4; jj++) {
                ffma2(acc[r][jj], xv.x, w[jj].x);
                ffma2(acc[r][jj], xv.y, w[jj].y);
            }
        }
    }

    // epilogue
#pragma unroll
    for (int jj = 0; jj < 4; jj++) {
        int j = tx + jj * 24;
        float s = 0.f, s2 = 0.f;
#pragma unroll
        for (int r = 0; r < 8; r++) {
            int row = base + ty * 8 + r;
            if (row < NN) {
                unsigned int lo_b, hi_b;
                asm("mov.b64 {%0, %1}, %2;" : "=r"(lo_b), "=r"(hi_b) : "l"(acc[r][jj]));
                float v = __uint_as_float(lo_b) + __uint_as_float(hi_b);
                if (mode == 0) v += bs[j];
                else v += g_acc[row * DD + j];
                g_acc[row * DD + j] = v;
                if (mode == 2) { s += v; s2 += v * v; }
            }
        }
        if (mode == 2) {
            atomicAdd(&g_colsum[j], s);
            atomicAdd(&g_colsumsq[j], s2);
        }
    }
}

// ---------------- SpMM block: dst[col] += norm * src[row] -------------------
// 6 warps/block, 4 edges/warp (8 lanes each, 3 float4 per lane).
__device__ __forceinline__ void spmm_block(int sblk, const float* __restrict__ src,
                                           float* __restrict__ dst) {
    int wid = threadIdx.x >> 5;
    int lane = threadIdx.x & 31;
    int e = (sblk * 6 + wid) * 4 + (lane >> 3);
    if (e >= EE) return;

    uint2 ed = g_edge[e];
    float nrm = __int_as_float((int)ed.y);
    if (nrm == 0.f) return;
    int r = (int)(ed.x >> 16);
    int c = (int)(ed.x & 0xFFFFu);
    int chunk = lane & 7;

    const float4* srow = reinterpret_cast<const float4*>(src) + r * (DD / 4);
    float* drow = dst + c * DD;

#pragma unroll
    for (int s = 0; s < 3; s++) {
        int idx = chunk + 8 * s;
        float4 v = __ldg(srow + idx);
        float a = nrm * v.x, b = nrm * v.y, cc = nrm * v.z, d = nrm * v.w;
        float* addr = drow + idx * 4;
        asm volatile("red.global.add.v4.f32 [%0], {%1, %2, %3, %4};"
                     :: "l"(addr), "f"(a), "f"(b), "f"(cc), "f"(d)
                     : "memory");
    }
}

// ---------------- Phase A/B: spmm blocks + interleaved gemm blocks ----------
#define SPMM_BLOCKS ((EE + 23) / 24)             // 33334
#define GRID_AB (SPMM_BLOCKS + GBLK)             // 34116
#define ILV 43                                   // gemm block every 43rd bid

__global__ __launch_bounds__(GT, 3)
void phaseAB_kernel(int pass, const float* __restrict__ x,
                    const float* __restrict__ W, const float* __restrict__ bias) {
    extern __shared__ float smem[];
    int bid = blockIdx.x;
    int g = bid / ILV, r = bid % ILV;
    if (r == 0 && g < GBLK) {
        if (pass == 0) gemm_tile(smem, g, 0, x, W, bias);
        else           gemm_tile(smem, g, 1, x, W + DD * DD, bias);
    } else {
        int before = min(g + (r > 0 ? 1 : 0), GBLK);
        int sblk = bid - before;
        if (pass == 0) spmm_block(sblk, x, g_T1);
        else           spmm_block(sblk, g_T1, g_P);
    }
}

// ---------------- Phase C: final accumulation + stats -----------------------
__global__ __launch_bounds__(GT, 3)
void phaseC_kernel(const float* __restrict__ x, const float* __restrict__ W) {
    extern __shared__ float smem[];
    gemm_tile(smem, blockIdx.x, 2, x, W + 2 * DD * DD, nullptr);
}

// ---------------- BatchNorm finalize ---------------------------------------
__global__ void bn_stats_kernel(const float* __restrict__ gamma,
                                const float* __restrict__ beta) {
    int j = threadIdx.x;
    if (j >= DD) return;
    float inv_n = 1.0f / (float)NN;
    float mean = g_colsum[j] * inv_n;
    float var = g_colsumsq[j] * inv_n - mean * mean;
    var = fmaxf(var, 0.f);
    float istd = rsqrtf(var + 1e-5f);
    float sc = gamma[j] * istd;
    g_scale[j] = sc;
    g_shift[j] = beta[j] - mean * sc;
}

__global__ void bn_apply_kernel(float* __restrict__ out) {
    __shared__ float sc[DD], sh[DD];
    if (threadIdx.x < DD) {
        sc[threadIdx.x] = g_scale[threadIdx.x];
        sh[threadIdx.x] = g_shift[threadIdx.x];
    }
    __syncthreads();
    int tid = blockIdx.x * blockDim.x + threadIdx.x;
    int stride = gridDim.x * blockDim.x;
    const float4* in4 = reinterpret_cast<const float4*>(g_acc);
    float4* o4 = reinterpret_cast<float4*>(out);
    for (int i = tid; i < NV4; i += stride) {
        int c4 = i % (DD / 4);
        int j = c4 * 4;
        float4 v = in4[i];
        o4[i] = make_float4(v.x * sc[j]     + sh[j],
                            v.y * sc[j + 1] + sh[j + 1],
                            v.z * sc[j + 2] + sh[j + 2],
                            v.w * sc[j + 3] + sh[j + 3]);
    }
}

// ---------------- launch ----------------------------------------------------
extern "C" void kernel_launch(void* const* d_in, const int* in_sizes, int n_in,
                              void* d_out, int out_size) {
    const float* x     = (const float*)d_in[0];
    const int*   ei    = (const int*)d_in[1];
    const float* W     = (const float*)d_in[2];
    const float* bias  = (const float*)d_in[3];
    const float* gamma = (const float*)d_in[4];
    const float* beta  = (const float*)d_in[5];
    float* out = (float*)d_out;

    cudaFuncSetAttribute(phaseAB_kernel,
                         cudaFuncAttributeMaxDynamicSharedMemorySize, SMEM_BYTES);
    cudaFuncSetAttribute(phaseC_kernel,
                         cudaFuncAttributeMaxDynamicSharedMemorySize, SMEM_BYTES);

    zero_kernel<<<2048, 256>>>();
    deg_kernel<<<(EE + 255) / 256, 256>>>(ei);
    dis_kernel<<<(NN + 255) / 256, 256>>>();
    edge_build_kernel<<<(EE + 255) / 256, 256>>>(ei);
    // Phase A: T1 = L_hat@x  ||  acc = x@W0 + bias
    phaseAB_kernel<<<GRID_AB, GT, SMEM_BYTES>>>(0, x, W, bias);
    // Phase B: P = L_hat@T1  ||  acc += T1@W1
    phaseAB_kernel<<<GRID_AB, GT, SMEM_BYTES>>>(1, x, W, bias);
    // Phase C: acc += (2P - x)@W2, BN stats
    phaseC_kernel<<<GBLK, GT, SMEM_BYTES>>>(x, W);
    bn_stats_kernel<<<1, 128>>>(gamma, beta);
    bn_apply_kernel<<<2048, 256>>>(out);
}

// round 7
// speedup vs baseline: 1.2184x; 1.2184x over previous
#include <cuda_runtime.h>

#define NN 50000
#define EE 800000
#define DD 96
#define NV4 (NN * DD / 4)

// ---------------- scratch (device globals; no allocation allowed) ----------
__device__ __align__(256) float g_deg[NN];
__device__ __align__(256) float g_dis[NN];
__device__ __align__(256) uint2 g_edge[EE];      // {(r<<16)|c, norm bits}
__device__ __align__(256) float g_T1[NN * DD];
__device__ __align__(256) float g_P[NN * DD];
__device__ __align__(256) float g_pA[NN * DD];   // x@W0 + bias
__device__ __align__(256) float g_pB[NN * DD];   // T1@W1
__device__ __align__(256) float g_pC[NN * DD];   // (2P-x)@W2
__device__ __align__(256) float g_acc[NN * DD];  // combined pre-BN output
__device__ __align__(256) float g_colsum[DD];
__device__ __align__(256) float g_colsumsq[DD];
__device__ __align__(256) float g_scale[DD];
__device__ __align__(256) float g_shift[DD];

// ---------------- packed f32x2 FMA (SASS FFMA2) -----------------------------
__device__ __forceinline__ void ffma2(unsigned long long& d,
                                      unsigned long long a,
                                      unsigned long long b) {
    asm("fma.rn.f32x2 %0, %1, %2, %0;" : "+l"(d) : "l"(a), "l"(b));
}

// ---------------- zero scratch ---------------------------------------------
__global__ void zero_kernel() {
    int tid = blockIdx.x * blockDim.x + threadIdx.x;
    int stride = gridDim.x * blockDim.x;
    float4* t1 = reinterpret_cast<float4*>(g_T1);
    float4* p  = reinterpret_cast<float4*>(g_P);
    float4 z = make_float4(0.f, 0.f, 0.f, 0.f);
    for (int i = tid; i < NV4; i += stride) { t1[i] = z; p[i] = z; }
    for (int i = tid; i < NN; i += stride) g_deg[i] = 0.f;
    if (tid < DD) { g_colsum[tid] = 0.f; g_colsumsq[tid] = 0.f; }
}

// ---------------- degree / normalization -----------------------------------
__global__ void deg_kernel(const int* __restrict__ ei) {
    int e = blockIdx.x * blockDim.x + threadIdx.x;
    if (e >= EE) return;
    int r = ei[e], c = ei[EE + e];
    if (r != c) atomicAdd(&g_deg[r], 1.0f);
}

__global__ void dis_kernel() {
    int i = blockIdx.x * blockDim.x + threadIdx.x;
    if (i >= NN) return;
    float d = g_deg[i];
    g_dis[i] = (d > 0.f) ? rsqrtf(fmaxf(d, 1e-12f)) : 0.f;
}

__global__ void edge_build_kernel(const int* __restrict__ ei) {
    int e = blockIdx.x * blockDim.x + threadIdx.x;
    if (e >= EE) return;
    int r = ei[e], c = ei[EE + e];
    float nrm = (r != c) ? (-g_dis[r] * g_dis[c]) : 0.f;
    g_edge[e] = make_uint2(((unsigned)r << 16) | (unsigned)c,
                           (unsigned)__float_as_int(nrm));
}

// ---------------- SpMM: dst[col] += norm[e] * src[row] ---------------------
// Warp handles 4 edges; 8 lanes per edge; each lane moves 3 float4.
__global__ void spmm_kernel(int pass, const float* __restrict__ x) {
    const float4* src = (pass == 0) ? reinterpret_cast<const float4*>(x)
                                    : reinterpret_cast<const float4*>(g_T1);
    float* dst = (pass == 0) ? g_T1 : g_P;

    int warp_id = (blockIdx.x * blockDim.x + threadIdx.x) >> 5;
    int lane = threadIdx.x & 31;
    int e = warp_id * 4 + (lane >> 3);
    if (e >= EE) return;

    uint2 ed = g_edge[e];
    float nrm = __int_as_float((int)ed.y);
    if (nrm == 0.f) return;
    int r = (int)(ed.x >> 16);
    int c = (int)(ed.x & 0xFFFFu);
    int chunk = lane & 7;

    const float4* srow = src + r * (DD / 4);
    float* drow = dst + c * DD;

#pragma unroll
    for (int s = 0; s < 3; s++) {
        int idx = chunk + 8 * s;
        float4 v = __ldg(srow + idx);
        float a = nrm * v.x, b = nrm * v.y, cc = nrm * v.z, d = nrm * v.w;
        float* addr = drow + idx * 4;
        asm volatile("red.global.add.v4.f32 [%0], {%1, %2, %3, %4};"
                     :: "l"(addr), "f"(a), "f"(b), "f"(cc), "f"(d)
                     : "memory");
    }
}

// ---------------- matrix-split GEMM: part_m = src_m @ W_m ------------------
// grid (782, 3); blockIdx.y = matrix m. smem = one W (transposed, padded)
// + one 64-row tile = ~63KB -> 3 CTAs/SM (18 warps). FFMA2 inner loop.
#define GT 192
#define RPB 64
#define WS_STRIDE 100
#define GBLK ((NN + RPB - 1) / RPB)                    // 782
#define SMEM_FLOATS (DD * WS_STRIDE + DD + RPB * DD)   // 9600+96+6144
#define SMEM_BYTES (SMEM_FLOATS * 4)                   // 63360 B

__global__ __launch_bounds__(GT, 3)
void gemm_kernel(const float* __restrict__ x, const float* __restrict__ W,
                 const float* __restrict__ bias) {
    extern __shared__ float smem[];
    float* Ws = smem;                    // [96*100] transposed
    float* bs = Ws + DD * WS_STRIDE;     // [96]
    float* xs = bs + DD;                 // [64*96]

    int tid = threadIdx.x;
    int m = blockIdx.y;
    const float* Wm = W + m * DD * DD;

    // stage Wm transposed: Ws[j*100 + k] = Wm[k*96 + j]
    for (int i = tid; i < DD * DD; i += GT) {
        int k = i / DD, j = i - k * DD;
        Ws[j * WS_STRIDE + k] = Wm[i];
    }
    if (m == 0 && tid < DD) bs[tid] = bias[tid];

    int base = blockIdx.x * RPB;

    // stage 64 rows of src_m
    {
        float4* xs4 = reinterpret_cast<float4*>(xs);
        const float4* x4 = reinterpret_cast<const float4*>(x);
        const float4* t14 = reinterpret_cast<const float4*>(g_T1);
        const float4* p4 = reinterpret_cast<const float4*>(g_P);
        for (int i = tid; i < RPB * (DD / 4); i += GT) {
            int r = i / (DD / 4);
            int row = base + r;
            float4 v = make_float4(0.f, 0.f, 0.f, 0.f);
            if (row < NN) {
                int gi = row * (DD / 4) + (i - r * (DD / 4));
                if (m == 0) v = __ldg(x4 + gi);
                else if (m == 1) v = t14[gi];
                else {
                    float4 pv = p4[gi];
                    float4 xv = __ldg(x4 + gi);
                    v = make_float4(2.f * pv.x - xv.x, 2.f * pv.y - xv.y,
                                    2.f * pv.z - xv.z, 2.f * pv.w - xv.w);
                }
            }
            xs4[i] = v;
        }
    }
    __syncthreads();

    int tx = tid % 24;          // j in {tx, tx+24, tx+48, tx+72}
    int ty = tid / 24;          // rows base + ty*8 .. +8

    unsigned long long acc[8][4];
#pragma unroll
    for (int r = 0; r < 8; r++)
#pragma unroll
        for (int jj = 0; jj < 4; jj++) acc[r][jj] = 0ULL;

    const float* xrow = xs + ty * 8 * DD;

    for (int k = 0; k < DD; k += 4) {
        ulonglong2 w[4];
#pragma unroll
        for (int jj = 0; jj < 4; jj++)
            w[jj] = *reinterpret_cast<const ulonglong2*>(
                        &Ws[(tx + jj * 24) * WS_STRIDE + k]);
#pragma unroll
        for (int r = 0; r < 8; r++) {
            ulonglong2 xv = *reinterpret_cast<const ulonglong2*>(&xrow[r * DD + k]);
#pragma unroll
            for (int jj = 0; jj < 4; jj++) {
                ffma2(acc[r][jj], xv.x, w[jj].x);
                ffma2(acc[r][jj], xv.y, w[jj].y);
            }
        }
    }

    float* part = (m == 0) ? g_pA : (m == 1) ? g_pB : g_pC;

#pragma unroll
    for (int jj = 0; jj < 4; jj++) {
        int j = tx + jj * 24;
        float bj = (m == 0) ? bs[j] : 0.f;
#pragma unroll
        for (int r = 0; r < 8; r++) {
            int row = base + ty * 8 + r;
            if (row < NN) {
                unsigned int lo_b, hi_b;
                asm("mov.b64 {%0, %1}, %2;" : "=r"(lo_b), "=r"(hi_b) : "l"(acc[r][jj]));
                part[row * DD + j] = __uint_as_float(lo_b) + __uint_as_float(hi_b) + bj;
            }
        }
    }
}

// ---------------- combine partials + column stats ---------------------------
#define CROWS 256
__global__ __launch_bounds__(GT, 8)
void combine_kernel() {
    int tid = threadIdx.x;
    int j = tid % DD;
    int rh = tid / DD;                  // 0 or 1
    int base = blockIdx.x * CROWS;
    float s = 0.f, s2 = 0.f;
    for (int r = rh; r < CROWS; r += 2) {
        int row = base + r;
        if (row >= NN) break;
        int i = row * DD + j;
        float v = g_pA[i] + g_pB[i] + g_pC[i];
        g_acc[i] = v;
        s += v; s2 += v * v;
    }
    atomicAdd(&g_colsum[j], s);
    atomicAdd(&g_colsumsq[j], s2);
}

// ---------------- BatchNorm finalize ---------------------------------------
__global__ void bn_stats_kernel(const float* __restrict__ gamma,
                                const float* __restrict__ beta) {
    int j = threadIdx.x;
    if (j >= DD) return;
    float inv_n = 1.0f / (float)NN;
    float mean = g_colsum[j] * inv_n;
    float var = g_colsumsq[j] * inv_n - mean * mean;
    var = fmaxf(var, 0.f);
    float istd = rsqrtf(var + 1e-5f);
    float sc = gamma[j] * istd;
    g_scale[j] = sc;
    g_shift[j] = beta[j] - mean * sc;
}

__global__ void bn_apply_kernel(float* __restrict__ out) {
    __shared__ float sc[DD], sh[DD];
    if (threadIdx.x < DD) {
        sc[threadIdx.x] = g_scale[threadIdx.x];
        sh[threadIdx.x] = g_shift[threadIdx.x];
    }
    __syncthreads();
    int tid = blockIdx.x * blockDim.x + threadIdx.x;
    int stride = gridDim.x * blockDim.x;
    const float4* in4 = reinterpret_cast<const float4*>(g_acc);
    float4* o4 = reinterpret_cast<float4*>(out);
    for (int i = tid; i < NV4; i += stride) {
        int c4 = i % (DD / 4);
        int j = c4 * 4;
        float4 v = in4[i];
        o4[i] = make_float4(v.x * sc[j]     + sh[j],
                            v.y * sc[j + 1] + sh[j + 1],
                            v.z * sc[j + 2] + sh[j + 2],
                            v.w * sc[j + 3] + sh[j + 3]);
    }
}

// ---------------- launch ----------------------------------------------------
extern "C" void kernel_launch(void* const* d_in, const int* in_sizes, int n_in,
                              void* d_out, int out_size) {
    const float* x     = (const float*)d_in[0];
    const int*   ei    = (const int*)d_in[1];
    const float* W     = (const float*)d_in[2];
    const float* bias  = (const float*)d_in[3];
    const float* gamma = (const float*)d_in[4];
    const float* beta  = (const float*)d_in[5];
    float* out = (float*)d_out;

    cudaFuncSetAttribute(gemm_kernel,
                         cudaFuncAttributeMaxDynamicSharedMemorySize, SMEM_BYTES);

    zero_kernel<<<2048, 256>>>();
    deg_kernel<<<(EE + 255) / 256, 256>>>(ei);
    dis_kernel<<<(NN + 255) / 256, 256>>>();
    edge_build_kernel<<<(EE + 255) / 256, 256>>>(ei);
    // prop 1: T1 = L_hat @ x
    spmm_kernel<<<EE / 32, 256>>>(0, x);
    // prop 2: P = L_hat @ T1  (T2 = 2P - x staged inside GEMM m=2)
    spmm_kernel<<<EE / 32, 256>>>(1, x);
    // 3 partial GEMMs in one grid (782 x 3), 3 CTAs/SM
    gemm_kernel<<<dim3(GBLK, 3), GT, SMEM_BYTES>>>(x, W, bias);
    combine_kernel<<<(NN + CROWS - 1) / CROWS, GT>>>();
    bn_stats_kernel<<<1, 128>>>(gamma, beta);
    bn_apply_kernel<<<2048, 256>>>(out);
}